// round 7
// baseline (speedup 1.0000x reference)
#include <cuda_runtime.h>
#include <cuda_bf16.h>
#include <cstdint>

#define NTOK 32768
#define DDIM 256
#define KC   1024
#define HW   1024
#define DECAY_F 0.99f
#define ONE_M_DECAY 0.01f
#define EPS_F 1e-5f

// output offsets (concatenated float32 outputs in reference return order)
#define O_ZQ   0
#define O_IDX  8388608
#define O_LOSS 8421376
#define O_EMB  8421377
#define O_CS   8683521
#define O_EAVG 8684545

__device__ float g_es[KC * DDIM];
__device__ float g_cs[KC];
__device__ int   g_idx[NTOK];
__device__ float g_enorm[KC];
__device__ float g_partial[1024];
__device__ float g_n;

// A splits in mma-FRAGMENT-MAJOR layout: u32 idx = tblk16*2048 + ks*128 + lane*4 + frag
__device__ __align__(16) uint32_t g_ax0f[NTOK * 128];
__device__ __align__(16) uint32_t g_ax1f[NTOK * 128];
__device__ __align__(16) uint32_t g_ax2f[NTOK * 128];
// B splits row-major (code-major, 512B rows)
__device__ __align__(16) __nv_bfloat16 g_be0[KC * DDIM];
__device__ __align__(16) __nv_bfloat16 g_be1[KC * DDIM];
__device__ __align__(16) __nv_bfloat16 g_be2[KC * DDIM];

__device__ __forceinline__ uint32_t smem_u32(const void* p) {
    uint32_t a;
    asm("{ .reg .u64 t; cvta.to.shared.u64 t, %1; cvt.u32.u64 %0, t; }"
        : "=r"(a) : "l"(p));
    return a;
}

__device__ __forceinline__ void mma16816(float* c, const uint32_t* a,
                                         uint32_t b0, uint32_t b1) {
    asm volatile(
        "mma.sync.aligned.m16n8k16.row.col.f32.bf16.bf16.f32 "
        "{%0,%1,%2,%3}, {%4,%5,%6,%7}, {%8,%9}, {%0,%1,%2,%3};"
        : "+f"(c[0]), "+f"(c[1]), "+f"(c[2]), "+f"(c[3])
        : "r"(a[0]), "r"(a[1]), "r"(a[2]), "r"(a[3]), "r"(b0), "r"(b1));
}

#define LDSM_X4(r0, r1, r2, r3, addr) \
    asm volatile("ldmatrix.sync.aligned.m8n8.x4.shared.b16 {%0,%1,%2,%3}, [%4];" \
        : "=r"(r0), "=r"(r1), "=r"(r2), "=r"(r3) : "r"(addr))

#define CP_ASYNC16(dst, src) \
    asm volatile("cp.async.cg.shared.global [%0], [%1], 16;" \
                 :: "r"(dst), "l"(src) : "memory")
#define CP_COMMIT() asm volatile("cp.async.commit_group;" ::: "memory")

__device__ __forceinline__ void split3(float v, __nv_bfloat16& h,
                                       __nv_bfloat16& m, __nv_bfloat16& l) {
    h = __float2bfloat16_rn(v);
    float r = v - __bfloat162float(h);
    m = __float2bfloat16_rn(r);
    float r2 = r - __bfloat162float(m);
    l = __float2bfloat16_rn(r2);
}

__global__ void pre_kernel() { if (threadIdx.x == 0) g_n = 0.f; }

// ---------------------------------------------------------------------------
// Fused e-split + ||e||^2: one block per code row
// ---------------------------------------------------------------------------
__global__ __launch_bounds__(256) void split_e_enorm_kernel(const float* __restrict__ embed) {
    __shared__ float wsum[8];
    int c = blockIdx.x, tid = threadIdx.x;
    int i = c * DDIM + tid;
    float v = embed[i];
    __nv_bfloat16 h, m, l;
    split3(v, h, m, l);
    g_be0[i] = h; g_be1[i] = m; g_be2[i] = l;
    float s = v * v;
#pragma unroll
    for (int off = 16; off; off >>= 1) s += __shfl_xor_sync(0xffffffffu, s, off);
    if ((tid & 31) == 0) wsum[tid >> 5] = s;
    __syncthreads();
    if (tid == 0) {
        float t = 0.f;
#pragma unroll
        for (int w = 0; w < 8; w++) t += wsum[w];
        g_enorm[c] = t;
    }
}

// token-transpose + split + fragment-major pack
__global__ __launch_bounds__(256) void split_x_kernel(const float* __restrict__ z) {
    __shared__ float s[32][257];
    int tid = threadIdx.x;
    int t0 = blockIdx.x * 32;
    int bimg = t0 >> 10, hw0 = t0 & 1023;
    int d0 = tid >> 5, ti = tid & 31;
#pragma unroll
    for (int mrow = 0; mrow < 32; mrow++) {
        int d = mrow * 8 + d0;
        s[ti][d] = z[((size_t)bimg * DDIM + d) * HW + hw0 + ti];
    }
    __syncthreads();
    size_t obase = (size_t)(t0 >> 4) * 2048;
#pragma unroll
    for (int i = 0; i < 16; i++) {
        int j = i * 256 + tid;
        int tbl = j >> 11, r = j & 2047;
        int ks = r >> 7, L = (r >> 2) & 31, f = r & 3;
        int g = L >> 2, q = L & 3, half = f & 1, kh = f >> 1;
        int tl = tbl * 16 + half * 8 + g;
        int d = ks * 16 + kh * 8 + q * 2;
        float v0 = s[tl][d], v1 = s[tl][d + 1];
        __nv_bfloat16 h0, m0, l0, h1, m1, l1;
        split3(v0, h0, m0, l0);
        split3(v1, h1, m1, l1);
        g_ax0f[obase + j] = ((uint32_t)__bfloat16_as_ushort(h1) << 16) | __bfloat16_as_ushort(h0);
        g_ax1f[obase + j] = ((uint32_t)__bfloat16_as_ushort(m1) << 16) | __bfloat16_as_ushort(m0);
        g_ax2f[obase + j] = ((uint32_t)__bfloat16_as_ushort(l1) << 16) | __bfloat16_as_ushort(l0);
    }
}

// ---------------------------------------------------------------------------
// Distance + argmin: warp-MMA bf16x6 emulated fp32.
// Grid 256 x 128 thr, 2 CTAs/SM (100KB smem each) -> all 148 SMs busy.
// CTA = 128 tokens (4 warps x m32) x 1024 codes in 16 n-chunks of 64.
// B single-buffered 96KB via cp.async (stall hidden by sibling CTA);
// A from gmem/L2 with register double-buffer; 96 MMAs per 6 A-LDGs.
// ---------------------------------------------------------------------------
#define BUF_BYTES 98304
#define SMEM_TOTAL (4096 + BUF_BYTES)

__global__ __launch_bounds__(128, 2) void dist_hmma_kernel(float* __restrict__ out)
{
    extern __shared__ __align__(1024) char smem[];
    float* s_enorm = (float*)smem;
    uint32_t sb = smem_u32(smem);
    int tid = threadIdx.x, wid = tid >> 5, lane = tid & 31;
    int t0 = blockIdx.x * 128;
    int group = lane >> 2, tq = lane & 3;
    int bn = (lane & 7) + ((lane >> 4) << 3);
    int bkh = (lane >> 3) & 1;

#pragma unroll
    for (int i = 0; i < 8; i++) s_enorm[i * 128 + tid] = g_enorm[i * 128 + tid];

    size_t abase[2];
#pragma unroll
    for (int mt = 0; mt < 2; mt++)
        abase[mt] = (size_t)(blockIdx.x * 8 + wid * 2 + mt) * 2048 + lane * 4;

    float best[4];
    int   bestk[4];
#pragma unroll
    for (int i = 0; i < 4; i++) { best[i] = 3.4e38f; bestk[i] = 0; }

    const char* bsrc[3] = {(const char*)g_be0, (const char*)g_be1, (const char*)g_be2};

    // ---- stage chunk 0: 3 splits x 64 codes x 512B = 96KB ----
#pragma unroll
    for (int it = 0; it < 48; it++) {
        int id = it * 128 + tid;
        int s = id >> 11, rem = id & 2047, n = rem >> 5, col = rem & 31;
        uint32_t dst = sb + 4096 + s * 32768 + n * 512 + ((col ^ (n & 7)) << 4);
        CP_ASYNC16(dst, bsrc[s] + (size_t)n * 512 + col * 16);
    }
    CP_COMMIT();

#pragma unroll 1
    for (int nc = 0; nc < 16; nc++) {
        asm volatile("cp.async.wait_group 0;" ::: "memory");
        __syncthreads();

        uint32_t bbase = sb + 4096;
        float acc[4][2][8];
#pragma unroll
        for (int nt = 0; nt < 4; nt++)
#pragma unroll
            for (int mt = 0; mt < 2; mt++)
#pragma unroll
                for (int j = 0; j < 8; j++) acc[nt][mt][j] = 0.f;

        // register double-buffer on A (hide L2 latency under MMA block)
        uint4 acur[3][2], anxt[3][2];
#pragma unroll
        for (int mt = 0; mt < 2; mt++) {
            acur[0][mt] = *(const uint4*)(g_ax0f + abase[mt]);
            acur[1][mt] = *(const uint4*)(g_ax1f + abase[mt]);
            acur[2][mt] = *(const uint4*)(g_ax2f + abase[mt]);
        }

#pragma unroll 1
        for (int ks = 0; ks < 16; ks++) {
            if (ks < 15) {
#pragma unroll
                for (int mt = 0; mt < 2; mt++) {
                    size_t o = abase[mt] + (ks + 1) * 128;
                    anxt[0][mt] = *(const uint4*)(g_ax0f + o);
                    anxt[1][mt] = *(const uint4*)(g_ax1f + o);
                    anxt[2][mt] = *(const uint4*)(g_ax2f + o);
                }
            }
#pragma unroll
            for (int nt = 0; nt < 4; nt++) {
                int nl = nt * 16 + bn;
                uint32_t baddr = bbase + nl * 512 + (((ks * 2 + bkh) ^ (nl & 7)) << 4);
                uint32_t b[3][4];
                LDSM_X4(b[0][0], b[0][1], b[0][2], b[0][3], baddr);
                LDSM_X4(b[1][0], b[1][1], b[1][2], b[1][3], baddr + 32768);
                LDSM_X4(b[2][0], b[2][1], b[2][2], b[2][3], baddr + 65536);
#pragma unroll
                for (int mt = 0; mt < 2; mt++) {
                    const uint32_t* a0 = (const uint32_t*)&acur[0][mt];
                    const uint32_t* a1 = (const uint32_t*)&acur[1][mt];
                    const uint32_t* a2 = (const uint32_t*)&acur[2][mt];
                    float* c0 = acc[nt][mt];
                    float* c1 = acc[nt][mt] + 4;
                    // 6 split-terms: hh, hm, mh, mm, lh, hl
                    mma16816(c0, a0, b[0][0], b[0][1]);
                    mma16816(c1, a0, b[0][2], b[0][3]);
                    mma16816(c0, a0, b[1][0], b[1][1]);
                    mma16816(c1, a0, b[1][2], b[1][3]);
                    mma16816(c0, a1, b[0][0], b[0][1]);
                    mma16816(c1, a1, b[0][2], b[0][3]);
                    mma16816(c0, a1, b[1][0], b[1][1]);
                    mma16816(c1, a1, b[1][2], b[1][3]);
                    mma16816(c0, a2, b[0][0], b[0][1]);
                    mma16816(c1, a2, b[0][2], b[0][3]);
                    mma16816(c0, a0, b[2][0], b[2][1]);
                    mma16816(c1, a0, b[2][2], b[2][3]);
                }
            }
#pragma unroll
            for (int s = 0; s < 3; s++)
#pragma unroll
                for (int mt = 0; mt < 2; mt++) acur[s][mt] = anxt[s][mt];
        }
        // ---- fold argmin: dist = ||e||^2 - 2 acc ----
        int n0 = nc * 64;
#pragma unroll
        for (int nt = 0; nt < 4; nt++)
#pragma unroll
            for (int mt = 0; mt < 2; mt++)
#pragma unroll
                for (int nh = 0; nh < 2; nh++) {
                    int cb = n0 + nt * 16 + nh * 8 + tq * 2;
                    float2 en = *(const float2*)&s_enorm[cb];
                    float* c = &acc[nt][mt][nh * 4];
                    float d0 = en.x - 2.f * c[0];
                    float d1 = en.y - 2.f * c[1];
                    float d2 = en.x - 2.f * c[2];
                    float d3 = en.y - 2.f * c[3];
                    int bi = mt * 2;
                    if (d0 < best[bi]) { best[bi] = d0; bestk[bi] = cb; }
                    if (d1 < best[bi]) { best[bi] = d1; bestk[bi] = cb + 1; }
                    if (d2 < best[bi + 1]) { best[bi + 1] = d2; bestk[bi + 1] = cb; }
                    if (d3 < best[bi + 1]) { best[bi + 1] = d3; bestk[bi + 1] = cb + 1; }
                }
        __syncthreads();   // all warps done with buffer
        if (nc < 15) {     // stage next chunk into the single buffer
            int n0n = (nc + 1) * 64;
#pragma unroll
            for (int it = 0; it < 48; it++) {
                int id = it * 128 + tid;
                int s = id >> 11, rem = id & 2047, n = rem >> 5, col = rem & 31;
                uint32_t dst = sb + 4096 + s * 32768 + n * 512 + ((col ^ (n & 7)) << 4);
                CP_ASYNC16(dst, bsrc[s] + (size_t)(n0n + n) * 512 + col * 16);
            }
            CP_COMMIT();
        }
    }

    // quad reduce (lanes in a quad share token rows)
#pragma unroll
    for (int off = 1; off <= 2; off <<= 1)
#pragma unroll
        for (int i = 0; i < 4; i++) {
            float ov = __shfl_xor_sync(0xffffffffu, best[i], off);
            int   ok = __shfl_xor_sync(0xffffffffu, bestk[i], off);
            if (ov < best[i] || (ov == best[i] && ok < bestk[i])) {
                best[i] = ov; bestk[i] = ok;
            }
        }
    if ((lane & 3) == 0) {
#pragma unroll
        for (int mt = 0; mt < 2; mt++)
#pragma unroll
            for (int h = 0; h < 2; h++) {
                int t = t0 + wid * 32 + mt * 16 + h * 8 + group;
                int bk = bestk[mt * 2 + h];
                g_idx[t] = bk;
                out[O_IDX + t] = (float)bk;
                atomicAdd(&g_cs[bk], 1.0f);
            }
    }
}

// ---------------------------------------------------------------------------
// Gather z_q, vq_loss partials, es segment-sum (v4 atomics, shuffle reduce)
// ---------------------------------------------------------------------------
__global__ __launch_bounds__(256) void gather_kernel(
    const float* __restrict__ z, const float* __restrict__ embed,
    float* __restrict__ out)
{
    __shared__ float s2[DDIM][33];
    __shared__ int   kidx[32];
    __shared__ float wred[8];
    int tid = threadIdx.x;
    int t0 = blockIdx.x * 32;
    int bimg = t0 >> 10, hw0 = t0 & 1023;

    if (tid < 32) kidx[tid] = g_idx[t0 + tid];
    __syncthreads();
#pragma unroll
    for (int l = 0; l < 32; l++)
        s2[tid][l] = embed[(size_t)kidx[l] * DDIM + tid];   // coalesced rows
    __syncthreads();

    int ti = tid & 31, dq = (tid >> 5) * 4;
    int myk = kidx[ti];
    float* esrow = &g_es[(size_t)myk * DDIM];
    float lsum = 0.f;
    float* outz = out + O_ZQ;
    const float* zb = z + (size_t)bimg * DDIM * HW + hw0 + ti;
    float* ob = outz + (size_t)bimg * DDIM * HW + hw0 + ti;
#pragma unroll
    for (int m = 0; m < 8; m++) {
        int d = m * 32 + dq;
        float e0 = s2[d][ti], e1 = s2[d + 1][ti], e2 = s2[d + 2][ti], e3 = s2[d + 3][ti];
        size_t zo = (size_t)d * HW;
        float z0 = zb[zo], z1 = zb[zo + HW], z2 = zb[zo + 2 * HW], z3 = zb[zo + 3 * HW];
        ob[zo] = e0; ob[zo + HW] = e1; ob[zo + 2 * HW] = e2; ob[zo + 3 * HW] = e3;
        float f0 = z0 - e0, f1 = z1 - e1, f2 = z2 - e2, f3 = z3 - e3;
        lsum += f0 * f0 + f1 * f1 + f2 * f2 + f3 * f3;
        asm volatile("red.global.add.v4.f32 [%0], {%1, %2, %3, %4};"
                     :: "l"(esrow + d), "f"(z0), "f"(z1), "f"(z2), "f"(z3) : "memory");
    }
#pragma unroll
    for (int off = 16; off; off >>= 1) lsum += __shfl_xor_sync(0xffffffffu, lsum, off);
    if ((tid & 31) == 0) wred[tid >> 5] = lsum;
    __syncthreads();
    if (tid == 0) {
        float s = 0.f;
#pragma unroll
        for (int w = 0; w < 8; w++) s += wred[w];
        g_partial[blockIdx.x] = s;
    }
}

// fused loss finalization + EMA cluster-size (single block)
__global__ void ema_a_kernel(const float* __restrict__ cluster_size,
                             float* __restrict__ out) {
    __shared__ float red[1024];
    int k = threadIdx.x;
    float ncs = cluster_size[k] * DECAY_F + ONE_M_DECAY * g_cs[k];
    out[O_CS + k] = ncs;
    red[k] = ncs + g_partial[k];   // piggyback loss partials in same reduction? no—
    __syncthreads();
    // separate reductions: recompute cleanly
    red[k] = ncs;
    __syncthreads();
    for (int off = 512; off; off >>= 1) {
        if (k < off) red[k] += red[k + off];
        __syncthreads();
    }
    if (k == 0) g_n = red[0];
    __syncthreads();
    red[k] = g_partial[k];
    __syncthreads();
    for (int off = 512; off; off >>= 1) {
        if (k < off) red[k] += red[k + off];
        __syncthreads();
    }
    if (k == 0) out[O_LOSS] = red[0] / 8388608.0f;
}

__global__ void ema_b_kernel(const float* __restrict__ embed_avg,
                             float* __restrict__ out) {
    int idx = blockIdx.x * 256 + threadIdx.x;
    int k = idx >> 8;
    float nea = embed_avg[idx] * DECAY_F + ONE_M_DECAY * g_es[idx];
    out[O_EAVG + idx] = nea;
    float ncs = out[O_CS + k];
    float n = g_n;
    float csn = (ncs + EPS_F) / (n + KC * EPS_F) * n;
    out[O_EMB + idx] = nea / csn;
}

// ---------------------------------------------------------------------------
extern "C" void kernel_launch(void* const* d_in, const int* in_sizes, int n_in,
                              void* d_out, int out_size)
{
    const float* z            = (const float*)d_in[0];
    const float* embed        = (const float*)d_in[1];
    const float* cluster_size = (const float*)d_in[2];
    const float* embed_avg    = (const float*)d_in[3];
    float* out = (float*)d_out;

    cudaFuncSetAttribute(dist_hmma_kernel,
                         cudaFuncAttributeMaxDynamicSharedMemorySize, SMEM_TOTAL);

    void* p;
    cudaGetSymbolAddress(&p, g_es);
    cudaMemsetAsync(p, 0, KC * DDIM * sizeof(float));        // launch 1
    cudaGetSymbolAddress(&p, g_cs);
    cudaMemsetAsync(p, 0, KC * sizeof(float));               // launch 2

    pre_kernel<<<1, 32>>>();                                 // launch 3
    split_e_enorm_kernel<<<KC, 256>>>(embed);                // launch 4
    split_x_kernel<<<NTOK / 32, 256>>>(z);                   // launch 5
    dist_hmma_kernel<<<NTOK / 128, 128, SMEM_TOTAL>>>(out);  // launch 6 <- ncu
    gather_kernel<<<NTOK / 32, 256>>>(z, embed, out);
    ema_a_kernel<<<1, 1024>>>(cluster_size, out);
    ema_b_kernel<<<KC * DDIM / 256, 256>>>(embed_avg, out);
}